// round 16
// baseline (speedup 1.0000x reference)
#include <cuda_runtime.h>
#include <cuda_fp16.h>

namespace {
constexpr int BT = 256;   // threads per block
constexpr int C  = 96;
constexpr int HW = 56;
constexpr int SH = 3;

// strides in HALVES. Conflict-free mma loads need stride ≡ 8 (mod 16).
constexpr int RXh = 104;  // XW / QO / KN rows
constexpr int RSh = 72;   // SP (probs) rows
constexpr int RVh = 72;   // Vt rows
constexpr int RFf = 98;   // fp32 staging row stride (2-way LDS conflicts max)

// shared layout (half indices). Over-read audit: A-fragment rows reach 63,
// B rows reach 55/95; every access lands inside the allocation; garbage is
// either discarded (M-dim rows >=49) or multiplied by explicit zeros /
// excluded by the j<49 predicate before exp (K/N dims).
constexpr int XWh = 0;                  // x/LN fp16                      : 49 x 104
constexpr int QOh = XWh + 49 * RXh;     // Q fp16 -> attn out fp16        : 49 x 104
constexpr int KNh = QOh + 49 * RXh;     // K row-major fp16               : 56 x 104
constexpr int SPh = KNh + 56 * RXh;     // probs fp16 (cols 49..63 zero)  : 49 x 72
constexpr int VTh = SPh + 49 * RSh;     // V transposed [d][j] fp16       : 96 x 72
constexpr int RSHh = VTh + 96 * RVh;    // rowsum floats (128) = 256 halves
constexpr int SMH  = RSHh + 256;        // 26712 halves = 53424 B
constexpr int RSF  = RSHh / 2;          // float index of rowsum buffer
constexpr int FSTf = KNh / 2;           // float idx of fp32 proj staging (KN.. dead)
}

// pair barrier: the two warps sharing rt (cbh = 0,1), 64 threads, id 1+rt
#define PAIRBAR() asm volatile("bar.sync %0, %1;" :: "r"(rt + 1), "r"(64) : "memory")

// fp16 B operands packed in m16n8k16 fragment order:
// uint idx = ((((ch*2+cbh)*6 + k16)*3 + tp)*32 + lane)*4 + q
__device__ unsigned g_wH[4 * 2 * 6 * 3 * 32 * 4];       // 73.7 KB
__device__ unsigned g_bias2[4 * 3 * 49 * 28];           // half2 bias+mask, -1000 pad

__device__ __forceinline__ unsigned h2u(float a, float b) {
    __half2 h = __floats2half2_rn(a, b);
    return *reinterpret_cast<unsigned*>(&h);
}

__device__ __forceinline__ void mma16(float* c, unsigned a0, unsigned a1,
                                      unsigned a2, unsigned a3,
                                      unsigned b0, unsigned b1) {
    asm("mma.sync.aligned.m16n8k16.row.col.f32.f16.f16.f32 "
        "{%0,%1,%2,%3},{%4,%5,%6,%7},{%8,%9},{%0,%1,%2,%3};"
        : "+f"(c[0]), "+f"(c[1]), "+f"(c[2]), "+f"(c[3])
        : "r"(a0), "r"(a1), "r"(a2), "r"(a3), "r"(b0), "r"(b1));
}

__global__ void prep_tables(const float* __restrict__ qkv_w,
                            const float* __restrict__ proj_w,
                            const float* __restrict__ rel_table)
{
    int idx = blockIdx.x * blockDim.x + threadIdx.x;
    if (idx < 4 * 2 * 6 * 3 * 32 * 4) {
        int q    = idx & 3;
        int lane = (idx >> 2) & 31;
        int tp   = (idx >> 7) % 3;
        int k16  = (idx / 384) % 6;
        int cbh  = (idx / 2304) & 1;
        int ch   = idx / 4608;
        int g = lane >> 2, tg = lane & 3;
        int n = cbh * 48 + (2 * tp + (q >> 1)) * 8 + g;
        int k = k16 * 16 + 2 * tg + (q & 1) * 8;
        float lo = (ch < 3) ? qkv_w[(ch * 96 + n) * 96 + k]     : proj_w[n * 96 + k];
        float hi = (ch < 3) ? qkv_w[(ch * 96 + n) * 96 + k + 1] : proj_w[n * 96 + k + 1];
        g_wH[idx] = h2u(lo, hi);
    }
    if (idx < 4 * 3 * 49 * 28) {
        int jp = idx % 28;
        int i  = (idx / 28) % 49;
        int h  = (idx / 1372) % 3;
        int cls = idx / 4116;
        float v[2];
        #pragma unroll
        for (int s = 0; s < 2; ++s) {
            int j = 2 * jp + s;
            if (j < 49) {
                int yi = i / 7, xi = i - yi * 7, yj = j / 7, xj = j - yj * 7;
                float bias = rel_table[((yi - yj + 6) * 13 + (xi - xj + 6)) * 3 + h];
                int ri = ((cls & 2) ? (yi < 4 ? 1 : 2) : 0) * 3 + ((cls & 1) ? (xi < 4 ? 1 : 2) : 0);
                int rj = ((cls & 2) ? (yj < 4 ? 1 : 2) : 0) * 3 + ((cls & 1) ? (xj < 4 ? 1 : 2) : 0);
                if (ri != rj) bias -= 100.f;
                v[s] = bias;
            } else v[s] = -1000.f;
        }
        g_bias2[idx] = h2u(v[0], v[1]);
    }
}

__global__ void __launch_bounds__(BT, 4)
swin_fused(const float* __restrict__ x,
           const float* __restrict__ ln_g, const float* __restrict__ ln_b,
           const float* __restrict__ qkv_b, const float* __restrict__ proj_b,
           float* __restrict__ out)
{
    extern __shared__ __align__(16) __half smh[];
    float* smf = reinterpret_cast<float*>(smh);

    const int tid  = threadIdx.x;
    const int lane = tid & 31;
    const int wrp  = tid >> 5;

    const int wid = blockIdx.x;
    const int b   = wid >> 6;
    const int w64 = wid & 63;
    const int wy  = w64 >> 3;
    const int wx  = w64 & 7;
    const int cls = ((wy == 7) ? 2 : 0) | ((wx == 7) ? 1 : 0);
    const float* xb = x + (size_t)b * C * HW * HW;

    const int rt  = wrp & 3;
    const int cbh = wrp >> 2;
    const int cb  = cbh * 48;
    const int g   = lane >> 2;
    const int tg  = lane & 3;
    const int ar0 = 16 * rt + g;          // A/C row 0 (row 1 = +8)
    const int rbase = 16 * rt + 8 * cbh;  // this warp's 8 owned rows

    // per-lane window-position offsets (computed once)
    int off0, off1;
    {
        int iy0 = lane / 7,  ix0 = lane - iy0 * 7;
        int p1  = lane + 32;
        int iy1 = p1 / 7,    ix1 = p1 - iy1 * 7;
        int h0 = wy * 7 + iy0 + SH; if (h0 >= HW) h0 -= HW;
        int w0 = wx * 7 + ix0 + SH; if (w0 >= HW) w0 -= HW;
        int h1 = wy * 7 + iy1 + SH; if (h1 >= HW) h1 -= HW;
        int w1 = wx * 7 + ix1 + SH; if (w1 >= HW) w1 -= HW;
        off0 = h0 * HW + w0;
        off1 = h1 * HW + w1;
    }
    const bool p1ok = (lane + 32) < 49;

    // ---- zero padding regions ----
    for (int idx = tid; idx < 96 * 8; idx += BT) {    // Vt cols 48..63
        int d = idx >> 3, q = idx & 7;
        *(unsigned*)&smh[VTh + d * RVh + 48 + 2 * q] = 0;
    }
    for (int idx = tid; idx < 49 * 4; idx += BT) {    // SP cols 56..63
        int i = idx >> 2, q = idx & 3;
        *(unsigned*)&smh[SPh + i * RSh + 56 + 2 * q] = 0;
    }

    // ---- gather (roll folded in): warp owns 12 CONSECUTIVE channels,
    //      half2 stores (halves the conflicted STS count) ----
    {
        const int cbase = 12 * wrp;
        #pragma unroll
        for (int k = 0; k < 6; ++k) {
            int c = cbase + 2 * k;
            const float* pl = xb + (size_t)c * (HW * HW);
            *(unsigned*)&smh[XWh + lane * RXh + c] =
                h2u(__ldg(pl + off0), __ldg(pl + HW * HW + off0));
            if (p1ok)
                *(unsigned*)&smh[XWh + (lane + 32) * RXh + c] =
                    h2u(__ldg(pl + off1), __ldg(pl + HW * HW + off1));
        }
    }
    __syncthreads();  // BLOCK: gather complete

    // ---- LayerNorm on warp's 8 owned rows ----
    {
        float g0 = __ldg(ln_g + lane),      b0 = __ldg(ln_b + lane);
        float g1 = __ldg(ln_g + lane + 32), b1 = __ldg(ln_b + lane + 32);
        float g2 = __ldg(ln_g + lane + 64), b2 = __ldg(ln_b + lane + 64);
        #pragma unroll 1
        for (int rr = 0; rr < 8; ++rr) {
            int p = rbase + rr;
            if (p < 49) {   // warp-uniform
                float v0 = __half2float(smh[XWh + p*RXh + lane]);
                float v1 = __half2float(smh[XWh + p*RXh + lane + 32]);
                float v2 = __half2float(smh[XWh + p*RXh + lane + 64]);
                float s = v0 + v1 + v2;
                #pragma unroll
                for (int o = 16; o; o >>= 1) s += __shfl_xor_sync(0xffffffffu, s, o);
                float mu = s * (1.f / 96.f);
                float d0 = v0 - mu, d1 = v1 - mu, d2 = v2 - mu;
                float vv = d0*d0 + d1*d1 + d2*d2;
                #pragma unroll
                for (int o = 16; o; o >>= 1) vv += __shfl_xor_sync(0xffffffffu, vv, o);
                float rstd = rsqrtf(vv * (1.f / 96.f) + 1e-5f);
                smh[XWh + p*RXh + lane]      = __float2half_rn(d0 * rstd * g0 + b0);
                smh[XWh + p*RXh + lane + 32] = __float2half_rn(d1 * rstd * g1 + b1);
                smh[XWh + p*RXh + lane + 64] = __float2half_rn(d2 * rstd * g2 + b2);
            }
        }
    }
    PAIRBAR();  // QKV mma A reads pair rows only

    const float qscale = 0.17677669529663687f;  // 32^-0.5

    // ---- QKV GEMMs via fp16 m16n8k16 mma ----
    #pragma unroll 1
    for (int ch = 0; ch < 3; ++ch) {
        const uint4* wb4 = reinterpret_cast<const uint4*>(g_wH)
                           + ((ch * 2 + cbh) * 18) * 32 + lane;
        float acc[6][4];
        #pragma unroll
        for (int t = 0; t < 6; ++t)
            { acc[t][0]=0.f; acc[t][1]=0.f; acc[t][2]=0.f; acc[t][3]=0.f; }

        #pragma unroll 2
        for (int k16 = 0; k16 < 6; ++k16) {
            const __half* ab = &smh[XWh + ar0 * RXh + k16 * 16 + 2 * tg];
            unsigned a0 = *(const unsigned*)ab;
            unsigned a1 = *(const unsigned*)(ab + 8 * RXh);
            unsigned a2 = *(const unsigned*)(ab + 8);
            unsigned a3 = *(const unsigned*)(ab + 8 * RXh + 8);
            #pragma unroll
            for (int tp = 0; tp < 3; ++tp) {
                uint4 w = __ldg(wb4 + (k16 * 3 + tp) * 32);
                mma16(acc[2*tp],   a0, a1, a2, a3, w.x, w.y);
                mma16(acc[2*tp+1], a0, a1, a2, a3, w.z, w.w);
            }
        }

        if (ch == 0) {          // Q: scaled, fp16 into QO
            #pragma unroll
            for (int t = 0; t < 6; ++t) {
                int c0 = cb + 8 * t + 2 * tg;
                float2 bb = __ldg((const float2*)(qkv_b + c0));
                if (ar0 < 49)
                    *(unsigned*)&smh[QOh + ar0 * RXh + c0] =
                        h2u((acc[t][0] + bb.x) * qscale, (acc[t][1] + bb.y) * qscale);
                if (ar0 + 8 < 49)
                    *(unsigned*)&smh[QOh + (ar0+8) * RXh + c0] =
                        h2u((acc[t][2] + bb.x) * qscale, (acc[t][3] + bb.y) * qscale);
            }
        } else if (ch == 1) {   // K: row-major fp16 into KN
            #pragma unroll
            for (int t = 0; t < 6; ++t) {
                int c0 = cb + 8 * t + 2 * tg;
                float2 bb = __ldg((const float2*)(qkv_b + 96 + c0));
                if (ar0 < 49)
                    *(unsigned*)&smh[KNh + ar0 * RXh + c0] =
                        h2u(acc[t][0] + bb.x, acc[t][1] + bb.y);
                if (ar0 + 8 < 49)
                    *(unsigned*)&smh[KNh + (ar0+8) * RXh + c0] =
                        h2u(acc[t][2] + bb.x, acc[t][3] + bb.y);
            }
        } else {                // V: scatter transposed into Vt
            #pragma unroll
            for (int t = 0; t < 6; ++t) {
                int c0 = cb + 8 * t + 2 * tg;
                float2 bb = __ldg((const float2*)(qkv_b + 192 + c0));
                if (ar0 < 49) {
                    smh[VTh + c0 * RVh + ar0]       = __float2half_rn(acc[t][0] + bb.x);
                    smh[VTh + (c0+1) * RVh + ar0]   = __float2half_rn(acc[t][1] + bb.y);
                }
                if (ar0 + 8 < 49) {
                    smh[VTh + c0 * RVh + ar0+8]     = __float2half_rn(acc[t][2] + bb.x);
                    smh[VTh + (c0+1) * RVh + ar0+8] = __float2half_rn(acc[t][3] + bb.y);
                }
            }
        }
    }
    __syncthreads();  // BLOCK: Q, K, Vt published

    // ---- attention per head: unnormalized probs, normalize at PV output ----
    #pragma unroll 1
    for (int h = 0; h < 3; ++h) {
        const int hb = h * 32;

        unsigned qa[2][4];
        #pragma unroll
        for (int m = 0; m < 2; ++m) {
            const __half* ab = &smh[QOh + ar0 * RXh + hb + m * 16 + 2 * tg];
            qa[m][0] = *(const unsigned*)ab;
            qa[m][1] = *(const unsigned*)(ab + 8 * RXh);
            qa[m][2] = *(const unsigned*)(ab + 8);
            qa[m][3] = *(const unsigned*)(ab + 8 * RXh + 8);
        }
        const int ntiles = cbh ? 3 : 4;
        const int n8beg  = cbh ? 4 : 0;
        float s0 = 0.f, s1 = 0.f;
        const unsigned* bt2 = g_bias2 + (cls * 3 + h) * 49 * 28;
        const int bi0 = (ar0     < 49 ? ar0     : 48) * 28;
        const int bi1 = (ar0 + 8 < 49 ? ar0 + 8 : 48) * 28;

        #pragma unroll
        for (int tt = 0; tt < 4; ++tt) {
            if (tt < ntiles) {          // warp-uniform
                int n8 = n8beg + tt;
                float c[4] = {0.f, 0.f, 0.f, 0.f};
                const __half* kb = &smh[KNh + (8 * n8 + g) * RXh + hb + 2 * tg];
                mma16(c, qa[0][0], qa[0][1], qa[0][2], qa[0][3],
                      *(const unsigned*)kb, *(const unsigned*)(kb + 8));
                mma16(c, qa[1][0], qa[1][1], qa[1][2], qa[1][3],
                      *(const unsigned*)(kb + 16), *(const unsigned*)(kb + 24));
                int j0 = 8 * n8 + 2 * tg;
                unsigned u0 = __ldg(bt2 + bi0 + 4 * n8 + tg);
                unsigned u1 = __ldg(bt2 + bi1 + 4 * n8 + tg);
                float2 f0 = __half22float2(*(const __half2*)&u0);
                float2 f1 = __half22float2(*(const __half2*)&u1);
                // e forced 0 for j>=49 (garbage K rows may be NaN there)
                float e0 = (j0     < 49) ? __expf(c[0] + f0.x) : 0.f;
                float e1 = (j0 + 1 < 49) ? __expf(c[1] + f0.y) : 0.f;
                float e2 = (j0     < 49) ? __expf(c[2] + f1.x) : 0.f;
                float e3 = (j0 + 1 < 49) ? __expf(c[3] + f1.y) : 0.f;
                s0 += e0 + e1;
                s1 += e2 + e3;
                // unnormalized fp16 probs straight to SP
                if (ar0 < 49)
                    *(unsigned*)&smh[SPh + ar0 * RSh + j0] = h2u(e0, e1);
                if (ar0 + 8 < 49)
                    *(unsigned*)&smh[SPh + (ar0+8) * RSh + j0] = h2u(e2, e3);
            }
        }
        // rowsum across tg lanes, publish for the partner warp
        s0 += __shfl_xor_sync(0xffffffffu, s0, 1);
        s0 += __shfl_xor_sync(0xffffffffu, s0, 2);
        s1 += __shfl_xor_sync(0xffffffffu, s1, 1);
        s1 += __shfl_xor_sync(0xffffffffu, s1, 2);
        if (tg == 0) {
            smf[RSF + cbh * 64 + rt * 16 + g]     = s0;
            smf[RSF + cbh * 64 + rt * 16 + 8 + g] = s1;
        }
        PAIRBAR();  // probs + partial rowsums visible to the pair
        float inv0 = 1.f / (s0 + smf[RSF + (1 - cbh) * 64 + rt * 16 + g]);
        float inv1 = 1.f / (s1 + smf[RSF + (1 - cbh) * 64 + rt * 16 + 8 + g]);

        // O = P_unnorm @ V, scaled by 1/rowsum at output
        unsigned pa[4][4];
        #pragma unroll
        for (int m = 0; m < 4; ++m) {
            const __half* pb = &smh[SPh + ar0 * RSh + m * 16 + 2 * tg];
            pa[m][0] = *(const unsigned*)pb;
            pa[m][1] = *(const unsigned*)(pb + 8 * RSh);
            pa[m][2] = *(const unsigned*)(pb + 8);
            pa[m][3] = *(const unsigned*)(pb + 8 * RSh + 8);
        }
        #pragma unroll
        for (int nn = 0; nn < 2; ++nn) {
            int n8 = 2 * cbh + nn;
            float c[4] = {0.f, 0.f, 0.f, 0.f};
            const __half* vb = &smh[VTh + (hb + 8 * n8 + g) * RVh + 2 * tg];
            #pragma unroll
            for (int m = 0; m < 4; ++m)
                mma16(c, pa[m][0], pa[m][1], pa[m][2], pa[m][3],
                      *(const unsigned*)(vb + 16 * m), *(const unsigned*)(vb + 16 * m + 8));
            int d0 = hb + 8 * n8 + 2 * tg;
            if (ar0 < 49)
                *(unsigned*)&smh[QOh + ar0 * RXh + d0] = h2u(c[0] * inv0, c[1] * inv0);
            if (ar0 + 8 < 49)
                *(unsigned*)&smh[QOh + (ar0+8) * RXh + d0] = h2u(c[2] * inv1, c[3] * inv1);
        }
        PAIRBAR();  // pair done reading SP + rowsums; next head may overwrite
    }
    __syncthreads();  // BLOCK: attention done (staging reuses KN/SP/Vt)

    // ---- proj GEMM (fp16 mma), fp32 staging into dead KN/SP/Vt region ----
    {
        const uint4* wb4 = reinterpret_cast<const uint4*>(g_wH)
                           + ((3 * 2 + cbh) * 18) * 32 + lane;
        float acc[6][4];
        #pragma unroll
        for (int t = 0; t < 6; ++t)
            { acc[t][0]=0.f; acc[t][1]=0.f; acc[t][2]=0.f; acc[t][3]=0.f; }

        #pragma unroll 2
        for (int k16 = 0; k16 < 6; ++k16) {
            const __half* ab = &smh[QOh + ar0 * RXh + k16 * 16 + 2 * tg];
            unsigned a0 = *(const unsigned*)ab;
            unsigned a1 = *(const unsigned*)(ab + 8 * RXh);
            unsigned a2 = *(const unsigned*)(ab + 8);
            unsigned a3 = *(const unsigned*)(ab + 8 * RXh + 8);
            #pragma unroll
            for (int tp = 0; tp < 3; ++tp) {
                uint4 w = __ldg(wb4 + (k16 * 3 + tp) * 32);
                mma16(acc[2*tp],   a0, a1, a2, a3, w.x, w.y);
                mma16(acc[2*tp+1], a0, a1, a2, a3, w.z, w.w);
            }
        }

        #pragma unroll
        for (int t = 0; t < 6; ++t) {
            int c0 = cb + 8 * t + 2 * tg;
            float2 bb = __ldg((const float2*)(proj_b + c0));
            if (ar0 < 49)
                *(float2*)&smf[FSTf + ar0 * RFf + c0] =
                    make_float2(acc[t][0] + bb.x, acc[t][1] + bb.y);
            if (ar0 + 8 < 49)
                *(float2*)&smf[FSTf + (ar0+8) * RFf + c0] =
                    make_float2(acc[t][2] + bb.x, acc[t][3] + bb.y);
        }
    }
    __syncthreads();  // BLOCK: staging complete

    // ---- window reverse + unshift scatter: 12 consecutive channels/warp,
    //      float2 staging reads (2-way conflicts max) ----
    {
        const int cbase = 12 * wrp;
        #pragma unroll
        for (int k = 0; k < 6; ++k) {
            int c = cbase + 2 * k;
            float* op = out + ((size_t)b * C + c) * (HW * HW);
            float2 v0 = *(const float2*)&smf[FSTf + lane * RFf + c];
            op[off0] = v0.x;
            (op + HW * HW)[off0] = v0.y;
            if (p1ok) {
                float2 v1 = *(const float2*)&smf[FSTf + (lane + 32) * RFf + c];
                op[off1] = v1.x;
                (op + HW * HW)[off1] = v1.y;
            }
        }
    }
}

extern "C" void kernel_launch(void* const* d_in, const int* in_sizes, int n_in,
                              void* d_out, int out_size)
{
    const float* x      = (const float*)d_in[0];
    const float* ln_g   = (const float*)d_in[1];
    const float* ln_b   = (const float*)d_in[2];
    const float* qkv_w  = (const float*)d_in[3];
    const float* qkv_b  = (const float*)d_in[4];
    const float* proj_w = (const float*)d_in[5];
    const float* proj_b = (const float*)d_in[6];
    const float* rel    = (const float*)d_in[7];
    float* out = (float*)d_out;

    const int B = in_sizes[0] / (C * HW * HW);   // 128
    const size_t smem = (size_t)SMH * sizeof(__half);   // 53424 B

    prep_tables<<<144, 256>>>(qkv_w, proj_w, rel);

    cudaFuncSetAttribute(swin_fused, cudaFuncAttributeMaxDynamicSharedMemorySize, (int)smem);
    swin_fused<<<B * 64, BT, smem>>>(x, ln_g, ln_b, qkv_b, proj_b, out);
}